// round 11
// baseline (speedup 1.0000x reference)
#include <cuda_runtime.h>
#include <math.h>
#include <stdint.h>

#define BB   32
#define NN   1024
#define DD   64
#define HH   128
#define OUTD 8
#define KK   16
#define CAP  128
#define NODES (BB*NN)

// ---------------- scratch (static device globals; no runtime alloc) ----------
__device__ float    g_maskf[NODES];
__device__ float    g_px[NODES];
__device__ float    g_py[NODES];
__device__ float    g_dinv[NODES];
__device__ float    g_coef[NODES];           // dinv * maskf (source-side coefficient)
__device__ int      g_cnt[NODES];
__device__ unsigned g_mask[NODES*32];        // reverse adjacency bitmask (per target)
__device__ int      g_rev[NODES*CAP];        // reverse adjacency lists (sorted by construction)
__device__ float    g_a[NODES*HH];           // pregather output (GEMM input)
__device__ float    g_h[NODES*HH];           // layer activations

// ---------------- 1. mask / pos init + zero bitmask ---------------------------
__global__ void prep_kernel(const float* __restrict__ obs) {
    int m = blockIdx.x * 256 + threadIdx.x;          // 0..32767
    const float4* row = (const float4*)(obs + m * DD);
    bool any = false;
    float x0 = 0.f, y0 = 0.f;
    #pragma unroll
    for (int i = 0; i < 16; i++) {
        float4 v = row[i];
        if (i == 0) { x0 = v.x; y0 = v.y; }
        any = any || (v.x != 0.f) || (v.y != 0.f) || (v.z != 0.f) || (v.w != 0.f);
    }
    float mf = any ? 1.f : 0.f;
    g_maskf[m] = mf;
    g_px[m] = x0;
    g_py[m] = y0;
    int4 z = {0,0,0,0};
    int4* mk = (int4*)&g_mask[m * 32];
    #pragma unroll
    for (int i = 0; i < 8; i++) mk[i] = z;
}

// ---------------- 2. kNN top-(K+1) + fused edge scatter, warp per node --------
// 32-bit d2 keys (bit order == numeric order for non-negatives; NaN sorts
// last). Index j = (slot<<5)|lane recomputed, never stored. Tie-break: min j
// among bit-tied lanes == lax.top_k semantics exactly.
#define REGRP(G, DM, DS) do {                                    \
    unsigned bm = 0xFFFFFFFFu; int bs = 0;                       \
    _Pragma("unroll")                                            \
    for (int s = (G)*8; s < (G)*8 + 8; s++) {                    \
        bool ok = (((sel >> s) & 1u) == 0u) && (u[s] < bm);      \
        bm = ok ? u[s] : bm;                                     \
        bs = ok ? s    : bs;                                     \
    }                                                            \
    DM = bm; DS = bs;                                            \
} while (0)

__global__ __launch_bounds__(256) void topk_kernel() {
    __shared__ float sx[NN], sy[NN];
    int b = blockIdx.y;
    for (int j = threadIdx.x; j < NN; j += 256) {
        float mf = g_maskf[b*NN + j];
        float X = g_px[b*NN + j], Y = g_py[b*NN + j];
        float inf = __int_as_float(0x7F800000);
        sx[j] = (mf != 0.f) ? X : inf;
        sy[j] = (mf != 0.f) ? Y : inf;
    }
    __syncthreads();

    int warp = threadIdx.x >> 5, lane = threadIdx.x & 31;
    int n = blockIdx.x * 8 + warp;
    float xn = sx[n], yn = sy[n];
    bool src_valid = (g_maskf[b*NN + n] != 0.f);

    unsigned u[32];
    #pragma unroll
    for (int i = 0; i < 32; i++) {
        int j = (i << 5) | lane;
        float dx = xn - sx[j];
        float dy = yn - sy[j];
        float d2 = __fadd_rn(__fmul_rn(dx, dx), __fmul_rn(dy, dy));
        u[i] = __float_as_uint(d2);
    }

    unsigned sel = 0;
    unsigned gm0, gm1, gm2, gm3;
    int      gs0, gs1, gs2, gs3;
    REGRP(0, gm0, gs0);
    REGRP(1, gm1, gs1);
    REGRP(2, gm2, gs2);
    REGRP(3, gm3, gs3);
    unsigned lmin = gm0; int lslot = gs0;              // ascending groups + strict <
    if (gm1 < lmin) { lmin = gm1; lslot = gs1; }       //   => lowest slot on ties
    if (gm2 < lmin) { lmin = gm2; lslot = gs2; }
    if (gm3 < lmin) { lmin = gm3; lslot = gs3; }

    int mword = (b*NN) * 32 + ((n >> 5));              // partial target word addr parts
    unsigned mbit = 1u << (n & 31);

    #pragma unroll 1
    for (int r = 0; r < KK + 1; r++) {
        // phase 1: warp-min of d2 bits
        unsigned w = lmin;
        #pragma unroll
        for (int s = 16; s >= 1; s >>= 1) {
            unsigned o = __shfl_xor_sync(0xffffffffu, w, s);
            w = o < w ? o : w;
        }
        // phase 2: owner = min j among bit-tied lanes (ballot fast path)
        unsigned tied = __ballot_sync(0xffffffffu, lmin == w);
        int jwin;
        if (__popc(tied) == 1) {
            int owner = __ffs(tied) - 1;
            jwin = __shfl_sync(0xffffffffu, lslot, owner) << 5 | owner;
        } else {
            int cand = (lmin == w) ? ((lslot << 5) | lane) : 0x7FFFFFFF;
            #pragma unroll
            for (int s = 16; s >= 1; s >>= 1) {
                int o = __shfl_xor_sync(0xffffffffu, cand, s);
                cand = o < cand ? o : cand;
            }
            jwin = cand;
        }
        // fused scatter: mark source n in target jwin's bitmask
        if (r > 0 && src_valid && lane == 0)
            atomicOr(&g_mask[mword + jwin * 32], mbit);
        if (r < KK && lane == (jwin & 31)) {           // owner refills
            int slot = jwin >> 5;
            sel |= (1u << slot);
            int g = slot >> 3;
            if      (g == 0) REGRP(0, gm0, gs0);
            else if (g == 1) REGRP(1, gm1, gs1);
            else if (g == 2) REGRP(2, gm2, gs2);
            else             REGRP(3, gm3, gs3);
            lmin = gm0; lslot = gs0;
            if (gm1 < lmin) { lmin = gm1; lslot = gs1; }
            if (gm2 < lmin) { lmin = gm2; lslot = gs2; }
            if (gm3 < lmin) { lmin = gm3; lslot = gs3; }
        }
    }
}

// ---------------- 3. listify: bitmask -> sorted list + deg/dinv/coef ----------
__global__ void listify_kernel() {
    int lane = threadIdx.x & 31;
    int m = (blockIdx.x * 256 + threadIdx.x) >> 5;   // warp per node
    unsigned wbits = g_mask[m * 32 + lane];
    int c = __popc(wbits);
    int pre = c;                                     // inclusive scan of counts
    #pragma unroll
    for (int s = 1; s < 32; s <<= 1) {
        int nv = __shfl_up_sync(0xffffffffu, pre, s);
        if (lane >= s) pre += nv;
    }
    int total = __shfl_sync(0xffffffffu, pre, 31);
    int base  = pre - c;
    if (lane == 0) {
        float mf = g_maskf[m];
        float d  = (float)total + 2.f * mf;
        float di = d > 0.f ? (1.0f / sqrtf(d)) : 0.f;
        g_dinv[m] = di;
        g_coef[m] = di * mf;
        g_cnt[m]  = total < CAP ? total : CAP;
    }
    int gb = (m & ~(NN - 1)) + (lane << 5);          // global source id base for this word
    while (wbits) {
        int j = __ffs(wbits) - 1;
        wbits &= wbits - 1;
        if (base < CAP) g_rev[m * CAP + base] = gb + j;
        base++;
    }
}

// ---------------- 4. pregather, float4 channels, 4-way MLP ---------------------
// g_a[m] = dinv[m] * sum_{src} coef[src]*X[src] + 2*dinv[m]^2 * X[m]
// 4 independent (coef, float4) load pairs in flight per iteration (MLP~4 to
// cover L2 latency); 256-thread blocks for warp-level latency hiding.
template<int DIN, bool FROMOBS>
__global__ __launch_bounds__(256) void pregather_kernel(const float* __restrict__ obs) {
    const float4* X = FROMOBS ? (const float4*)obs : (const float4*)g_h;
    constexpr int C4  = DIN / 4;                     // float4s per row (16 / 32)
    constexpr int NPB = 256 / C4;                    // nodes per block  (16 / 8)
    int local = threadIdx.x / C4;
    int c     = threadIdx.x % C4;                    // float4 channel index
    int m = blockIdx.x * NPB + local;
    __shared__ int   ssrc[NPB][CAP];                 // src * C4 (premultiplied)
    __shared__ float scf[NPB][CAP];
    int nsrc = g_cnt[m];
    for (int s = c; s < nsrc; s += C4) {
        int src = g_rev[m * CAP + s];
        ssrc[local][s] = src * C4;
        scf[local][s]  = g_coef[src];
    }
    __syncthreads();
    float4 a0 = {0.f,0.f,0.f,0.f}, a1 = {0.f,0.f,0.f,0.f};
    float4 a2 = {0.f,0.f,0.f,0.f}, a3 = {0.f,0.f,0.f,0.f};
    int s = 0;
    for (; s + 3 < nsrc; s += 4) {
        float  c0 = scf[local][s],   c1 = scf[local][s+1];
        float  c2 = scf[local][s+2], c3 = scf[local][s+3];
        float4 v0 = X[ssrc[local][s]   + c];
        float4 v1 = X[ssrc[local][s+1] + c];
        float4 v2 = X[ssrc[local][s+2] + c];
        float4 v3 = X[ssrc[local][s+3] + c];
        a0.x = fmaf(c0, v0.x, a0.x); a0.y = fmaf(c0, v0.y, a0.y);
        a0.z = fmaf(c0, v0.z, a0.z); a0.w = fmaf(c0, v0.w, a0.w);
        a1.x = fmaf(c1, v1.x, a1.x); a1.y = fmaf(c1, v1.y, a1.y);
        a1.z = fmaf(c1, v1.z, a1.z); a1.w = fmaf(c1, v1.w, a1.w);
        a2.x = fmaf(c2, v2.x, a2.x); a2.y = fmaf(c2, v2.y, a2.y);
        a2.z = fmaf(c2, v2.z, a2.z); a2.w = fmaf(c2, v2.w, a2.w);
        a3.x = fmaf(c3, v3.x, a3.x); a3.y = fmaf(c3, v3.y, a3.y);
        a3.z = fmaf(c3, v3.z, a3.z); a3.w = fmaf(c3, v3.w, a3.w);
    }
    for (; s < nsrc; s++) {
        float  cf = scf[local][s];
        float4 v  = X[ssrc[local][s] + c];
        a0.x = fmaf(cf, v.x, a0.x); a0.y = fmaf(cf, v.y, a0.y);
        a0.z = fmaf(cf, v.z, a0.z); a0.w = fmaf(cf, v.w, a0.w);
    }
    a0.x = (a0.x + a1.x) + (a2.x + a3.x);
    a0.y = (a0.y + a1.y) + (a2.y + a3.y);
    a0.z = (a0.z + a1.z) + (a2.z + a3.z);
    a0.w = (a0.w + a1.w) + (a2.w + a3.w);
    float  dm  = g_dinv[m];
    float  dm2 = 2.f * dm * dm;
    float4 xm  = X[m * C4 + c];
    float4 o;
    o.x = dm * a0.x + dm2 * xm.x;
    o.y = dm * a0.y + dm2 * xm.y;
    o.z = dm * a0.z + dm2 * xm.z;
    o.w = dm * a0.w + dm2 * xm.w;
    ((float4*)g_a)[m * C4 + c] = o;
}

// ---------------- 5. GEMM + bias + tanh (+ optional fused output head) --------
#define XS(k,r) smem_f[(k)*64 + (r)]
#define WS(k,c) smem_f[2048 + (k)*128 + (c)]
#define HS(r,c) smem_f[(r)*128 + (c)]

template<int DIN, bool FINAL>
__global__ __launch_bounds__(256) void gemm_kernel(const float* __restrict__ W,
                                                   const float* __restrict__ bias,
                                                   const float* __restrict__ Wout,
                                                   const float* __restrict__ bout,
                                                   float* __restrict__ out) {
    const float* X = (const float*)g_a;
    __shared__ __align__(16) float smem_f[8192];
    int tid  = threadIdx.x;
    int lane = tid & 31;           // cols lane*4 .. +3
    int warp = tid >> 5;           // rows warp*8 .. +7
    int row0 = blockIdx.x * 64;

    float4 bv = *(const float4*)(bias + lane * 4);

    float acc[8][4];
    #pragma unroll
    for (int r = 0; r < 8; r++)
        #pragma unroll
        for (int c = 0; c < 4; c++) acc[r][c] = 0.f;

    for (int kc = 0; kc < DIN; kc += 32) {
        #pragma unroll
        for (int t = 0; t < 2; t++) {              // X tile 64x32, transposed
            int f = tid + t * 256;                 // 0..511
            int r = f >> 3;
            int kq = (f & 7) << 2;
            float4 v = *(const float4*)(X + (row0 + r) * DIN + kc + kq);
            XS(kq+0, r) = v.x; XS(kq+1, r) = v.y;
            XS(kq+2, r) = v.z; XS(kq+3, r) = v.w;
        }
        #pragma unroll
        for (int t = 0; t < 4; t++) {              // W tile 32x128, direct
            int f = tid + t * 256;                 // 0..1023
            int k = f >> 5;
            int c = (f & 31) << 2;
            *(float4*)&WS(k, c) = *(const float4*)(W + (kc + k) * HH + c);
        }
        __syncthreads();
        #pragma unroll
        for (int k = 0; k < 32; k++) {
            float4 a0 = *(const float4*)&XS(k, warp*8);
            float4 a1 = *(const float4*)&XS(k, warp*8 + 4);
            float4 wv = *(const float4*)&WS(k, lane*4);
            float a[8] = {a0.x,a0.y,a0.z,a0.w,a1.x,a1.y,a1.z,a1.w};
            float bb[4] = {wv.x,wv.y,wv.z,wv.w};
            #pragma unroll
            for (int r = 0; r < 8; r++)
                #pragma unroll
                for (int c = 0; c < 4; c++)
                    acc[r][c] = fmaf(a[r], bb[c], acc[r][c]);
        }
        __syncthreads();
    }

    if (!FINAL) {
        #pragma unroll
        for (int r = 0; r < 8; r++) {
            float4 v;
            v.x = tanhf(acc[r][0] + bv.x);
            v.y = tanhf(acc[r][1] + bv.y);
            v.z = tanhf(acc[r][2] + bv.z);
            v.w = tanhf(acc[r][3] + bv.w);
            *(float4*)(g_h + (row0 + warp*8 + r) * HH + lane*4) = v;
        }
    } else {
        #pragma unroll
        for (int r = 0; r < 8; r++) {
            float4 v;
            v.x = tanhf(acc[r][0] + bv.x);
            v.y = tanhf(acc[r][1] + bv.y);
            v.z = tanhf(acc[r][2] + bv.z);
            v.w = tanhf(acc[r][3] + bv.w);
            *(float4*)&HS(warp*8 + r, lane*4) = v;
        }
        __syncthreads();
        float wreg[32];                           // Wout rows lane*4..+3 (8 outs each)
        #pragma unroll
        for (int i = 0; i < 8; i++)
            *(float4*)&wreg[i*4] = *(const float4*)(Wout + lane * 32 + i * 4);
        #pragma unroll
        for (int rr = 0; rr < 8; rr++) {
            int row = warp * 8 + rr;
            float4 hv = *(const float4*)&HS(row, lane*4);
            float hk[4] = {hv.x, hv.y, hv.z, hv.w};
            float a2[8];
            #pragma unroll
            for (int o = 0; o < 8; o++) a2[o] = 0.f;
            #pragma unroll
            for (int j = 0; j < 4; j++)
                #pragma unroll
                for (int o = 0; o < 8; o++)
                    a2[o] = fmaf(hk[j], wreg[j*8 + o], a2[o]);
            #pragma unroll
            for (int o = 0; o < 8; o++)
                #pragma unroll
                for (int s = 16; s >= 1; s >>= 1)
                    a2[o] += __shfl_xor_sync(0xffffffffu, a2[o], s);
            if (lane == 0) {
                int m = row0 + row;
                float mf = g_maskf[m];
                #pragma unroll
                for (int o = 0; o < 8; o++)
                    out[m * OUTD + o] = (a2[o] + bout[o]) * mf;
            }
        }
    }
}

// ---------------- launch ------------------------------------------------------
extern "C" void kernel_launch(void* const* d_in, const int* in_sizes, int n_in,
                              void* d_out, int out_size) {
    const float* obs  = (const float*)d_in[0];
    const float* W1   = (const float*)d_in[1];
    const float* b1   = (const float*)d_in[2];
    const float* W2   = (const float*)d_in[3];
    const float* b2   = (const float*)d_in[4];
    const float* Wout = (const float*)d_in[5];
    const float* bout = (const float*)d_in[6];
    float* out = (float*)d_out;

    prep_kernel   <<<NODES/256, 256>>>(obs);
    topk_kernel   <<<dim3(NN/8, BB), 256>>>();      // kNN + fused scatter
    listify_kernel<<<NODES/8, 256>>>();

    pregather_kernel<DD, true> <<<NODES/16, 256>>>(obs);             // 64-dim gather -> g_a
    gemm_kernel<DD, false><<<NODES/64, 256>>>(W1, b1, 0, 0, 0);      // g_a @ W1 -> g_h (tanh)
    pregather_kernel<HH, false><<<NODES/8, 256>>>(obs);              // 128-dim gather g_h -> g_a
    gemm_kernel<HH, true><<<NODES/64, 256>>>(W2, b2, Wout, bout, out); // -> out
}

// round 12
// speedup vs baseline: 1.0620x; 1.0620x over previous
#include <cuda_runtime.h>
#include <math.h>
#include <stdint.h>

#define BB   32
#define NN   1024
#define DD   64
#define HH   128
#define OUTD 8
#define KK   16
#define CAP  128
#define NODES (BB*NN)

// ---------------- scratch (static device globals; no runtime alloc) ----------
__device__ float    g_maskf[NODES];
__device__ float    g_px[NODES];
__device__ float    g_py[NODES];
__device__ float    g_dinv[NODES];
__device__ float    g_coef[NODES];           // dinv * maskf (source-side coefficient)
__device__ int      g_cnt[NODES];
__device__ unsigned g_mask[NODES*32];        // reverse adjacency bitmask (per target)
__device__ int      g_rev[NODES*CAP];        // reverse adjacency lists (sorted by construction)
__device__ float    g_a[NODES*HH];           // pregather output (GEMM input)
__device__ float    g_h[NODES*HH];           // layer activations

// ---------------- 1. mask / pos init + zero bitmask ---------------------------
__global__ void prep_kernel(const float* __restrict__ obs) {
    int m = blockIdx.x * 256 + threadIdx.x;          // 0..32767
    const float4* row = (const float4*)(obs + m * DD);
    bool any = false;
    float x0 = 0.f, y0 = 0.f;
    #pragma unroll
    for (int i = 0; i < 16; i++) {
        float4 v = row[i];
        if (i == 0) { x0 = v.x; y0 = v.y; }
        any = any || (v.x != 0.f) || (v.y != 0.f) || (v.z != 0.f) || (v.w != 0.f);
    }
    float mf = any ? 1.f : 0.f;
    g_maskf[m] = mf;
    g_px[m] = x0;
    g_py[m] = y0;
    int4 z = {0,0,0,0};
    int4* mk = (int4*)&g_mask[m * 32];
    #pragma unroll
    for (int i = 0; i < 8; i++) mk[i] = z;
}

// ---------------- 2. kNN top-(K+1) + fused edge scatter, warp per node --------
// 32-bit d2 keys (bit order == numeric order for non-negatives; NaN sorts
// last). Index j = (slot<<5)|lane recomputed, never stored. Tie-break: min j
// among bit-tied lanes == lax.top_k semantics exactly. Warp mins via
// single-instruction REDUX (__reduce_min_sync, sm_80+).
#define REGRP(G, DM, DS) do {                                    \
    unsigned bm = 0xFFFFFFFFu; int bs = 0;                       \
    _Pragma("unroll")                                            \
    for (int s = (G)*8; s < (G)*8 + 8; s++) {                    \
        bool ok = (((sel >> s) & 1u) == 0u) && (u[s] < bm);      \
        bm = ok ? u[s] : bm;                                     \
        bs = ok ? s    : bs;                                     \
    }                                                            \
    DM = bm; DS = bs;                                            \
} while (0)

__global__ __launch_bounds__(256) void topk_kernel() {
    __shared__ float sx[NN], sy[NN];
    int b = blockIdx.y;
    for (int j = threadIdx.x; j < NN; j += 256) {
        float mf = g_maskf[b*NN + j];
        float X = g_px[b*NN + j], Y = g_py[b*NN + j];
        float inf = __int_as_float(0x7F800000);
        sx[j] = (mf != 0.f) ? X : inf;
        sy[j] = (mf != 0.f) ? Y : inf;
    }
    __syncthreads();

    int warp = threadIdx.x >> 5, lane = threadIdx.x & 31;
    int n = blockIdx.x * 8 + warp;
    float xn = sx[n], yn = sy[n];
    bool src_valid = (g_maskf[b*NN + n] != 0.f);

    unsigned u[32];
    #pragma unroll
    for (int i = 0; i < 32; i++) {
        int j = (i << 5) | lane;
        float dx = xn - sx[j];
        float dy = yn - sy[j];
        float d2 = __fadd_rn(__fmul_rn(dx, dx), __fmul_rn(dy, dy));
        u[i] = __float_as_uint(d2);
    }

    unsigned sel = 0;
    unsigned gm0, gm1, gm2, gm3;
    int      gs0, gs1, gs2, gs3;
    REGRP(0, gm0, gs0);
    REGRP(1, gm1, gs1);
    REGRP(2, gm2, gs2);
    REGRP(3, gm3, gs3);
    unsigned lmin = gm0; int lslot = gs0;              // ascending groups + strict <
    if (gm1 < lmin) { lmin = gm1; lslot = gs1; }       //   => lowest slot on ties
    if (gm2 < lmin) { lmin = gm2; lslot = gs2; }
    if (gm3 < lmin) { lmin = gm3; lslot = gs3; }

    int mword = (b*NN) * 32 + ((n >> 5));              // partial target word addr parts
    unsigned mbit = 1u << (n & 31);

    #pragma unroll 1
    for (int r = 0; r < KK + 1; r++) {
        // phase 1: warp-min of d2 bits (single REDUX)
        unsigned w = __reduce_min_sync(0xffffffffu, lmin);
        // phase 2: min j among bit-tied lanes (single REDUX)
        int cand = (lmin == w) ? ((lslot << 5) | lane) : 0x7FFFFFFF;
        int jwin = __reduce_min_sync(0xffffffffu, cand);
        // fused scatter: mark source n in target jwin's bitmask
        if (r > 0 && src_valid && lane == 0)
            atomicOr(&g_mask[mword + jwin * 32], mbit);
        if (r < KK && lane == (jwin & 31)) {           // owner refills
            int slot = jwin >> 5;
            sel |= (1u << slot);
            int g = slot >> 3;
            if      (g == 0) REGRP(0, gm0, gs0);
            else if (g == 1) REGRP(1, gm1, gs1);
            else if (g == 2) REGRP(2, gm2, gs2);
            else             REGRP(3, gm3, gs3);
            lmin = gm0; lslot = gs0;
            if (gm1 < lmin) { lmin = gm1; lslot = gs1; }
            if (gm2 < lmin) { lmin = gm2; lslot = gs2; }
            if (gm3 < lmin) { lmin = gm3; lslot = gs3; }
        }
    }
}

// ---------------- 3. listify: bitmask -> sorted list + deg/dinv/coef ----------
__global__ void listify_kernel() {
    int lane = threadIdx.x & 31;
    int m = (blockIdx.x * 256 + threadIdx.x) >> 5;   // warp per node
    unsigned wbits = g_mask[m * 32 + lane];
    int c = __popc(wbits);
    int pre = c;                                     // inclusive scan of counts
    #pragma unroll
    for (int s = 1; s < 32; s <<= 1) {
        int nv = __shfl_up_sync(0xffffffffu, pre, s);
        if (lane >= s) pre += nv;
    }
    int total = __shfl_sync(0xffffffffu, pre, 31);
    int base  = pre - c;
    if (lane == 0) {
        float mf = g_maskf[m];
        float d  = (float)total + 2.f * mf;
        float di = d > 0.f ? (1.0f / sqrtf(d)) : 0.f;
        g_dinv[m] = di;
        g_coef[m] = di * mf;
        g_cnt[m]  = total < CAP ? total : CAP;
    }
    int gb = (m & ~(NN - 1)) + (lane << 5);          // global source id base for this word
    while (wbits) {
        int j = __ffs(wbits) - 1;
        wbits &= wbits - 1;
        if (base < CAP) g_rev[m * CAP + base] = gb + j;
        base++;
    }
}

// ---------------- 4. pregather, float4 channels (R10-proven config) -----------
// g_a[m] = dinv[m] * sum_{src} coef[src]*X[src] + 2*dinv[m]^2 * X[m]
template<int DIN, bool FROMOBS>
__global__ void pregather_kernel(const float* __restrict__ obs) {
    const float4* X = FROMOBS ? (const float4*)obs : (const float4*)g_h;
    constexpr int C4  = DIN / 4;                     // float4s per row (16 / 32)
    constexpr int NPB = 128 / C4;                    // nodes per block  (8 / 4)
    int local = threadIdx.x / C4;
    int c     = threadIdx.x % C4;                    // float4 channel index
    int m = blockIdx.x * NPB + local;
    __shared__ int   ssrc[NPB][CAP];                 // src * C4 (premultiplied)
    __shared__ float scf[NPB][CAP];
    int nsrc = g_cnt[m];
    for (int s = c; s < nsrc; s += C4) {
        int src = g_rev[m * CAP + s];
        ssrc[local][s] = src * C4;
        scf[local][s]  = g_coef[src];
    }
    __syncthreads();
    float4 agg  = {0.f, 0.f, 0.f, 0.f};
    float4 agg2 = {0.f, 0.f, 0.f, 0.f};
    int s = 0;
    for (; s + 1 < nsrc; s += 2) {
        float  cf0 = scf[local][s],     cf1 = scf[local][s + 1];
        float4 v0  = X[ssrc[local][s]     + c];
        float4 v1  = X[ssrc[local][s + 1] + c];
        agg.x  = fmaf(cf0, v0.x, agg.x);  agg.y  = fmaf(cf0, v0.y, agg.y);
        agg.z  = fmaf(cf0, v0.z, agg.z);  agg.w  = fmaf(cf0, v0.w, agg.w);
        agg2.x = fmaf(cf1, v1.x, agg2.x); agg2.y = fmaf(cf1, v1.y, agg2.y);
        agg2.z = fmaf(cf1, v1.z, agg2.z); agg2.w = fmaf(cf1, v1.w, agg2.w);
    }
    if (s < nsrc) {
        float  cf = scf[local][s];
        float4 v  = X[ssrc[local][s] + c];
        agg.x = fmaf(cf, v.x, agg.x); agg.y = fmaf(cf, v.y, agg.y);
        agg.z = fmaf(cf, v.z, agg.z); agg.w = fmaf(cf, v.w, agg.w);
    }
    agg.x += agg2.x; agg.y += agg2.y; agg.z += agg2.z; agg.w += agg2.w;
    float  dm  = g_dinv[m];
    float  dm2 = 2.f * dm * dm;
    float4 xm  = X[m * C4 + c];
    float4 o;
    o.x = dm * agg.x + dm2 * xm.x;
    o.y = dm * agg.y + dm2 * xm.y;
    o.z = dm * agg.z + dm2 * xm.z;
    o.w = dm * agg.w + dm2 * xm.w;
    ((float4*)g_a)[m * C4 + c] = o;
}

// ---------------- 5. GEMM + bias + tanh (+ optional fused output head) --------
#define XS(k,r) smem_f[(k)*64 + (r)]
#define WS(k,c) smem_f[2048 + (k)*128 + (c)]
#define HS(r,c) smem_f[(r)*128 + (c)]

template<int DIN, bool FINAL>
__global__ __launch_bounds__(256) void gemm_kernel(const float* __restrict__ W,
                                                   const float* __restrict__ bias,
                                                   const float* __restrict__ Wout,
                                                   const float* __restrict__ bout,
                                                   float* __restrict__ out) {
    const float* X = (const float*)g_a;
    __shared__ __align__(16) float smem_f[8192];
    int tid  = threadIdx.x;
    int lane = tid & 31;           // cols lane*4 .. +3
    int warp = tid >> 5;           // rows warp*8 .. +7
    int row0 = blockIdx.x * 64;

    float4 bv = *(const float4*)(bias + lane * 4);

    float acc[8][4];
    #pragma unroll
    for (int r = 0; r < 8; r++)
        #pragma unroll
        for (int c = 0; c < 4; c++) acc[r][c] = 0.f;

    for (int kc = 0; kc < DIN; kc += 32) {
        #pragma unroll
        for (int t = 0; t < 2; t++) {              // X tile 64x32, transposed
            int f = tid + t * 256;                 // 0..511
            int r = f >> 3;
            int kq = (f & 7) << 2;
            float4 v = *(const float4*)(X + (row0 + r) * DIN + kc + kq);
            XS(kq+0, r) = v.x; XS(kq+1, r) = v.y;
            XS(kq+2, r) = v.z; XS(kq+3, r) = v.w;
        }
        #pragma unroll
        for (int t = 0; t < 4; t++) {              // W tile 32x128, direct
            int f = tid + t * 256;                 // 0..1023
            int k = f >> 5;
            int c = (f & 31) << 2;
            *(float4*)&WS(k, c) = *(const float4*)(W + (kc + k) * HH + c);
        }
        __syncthreads();
        #pragma unroll
        for (int k = 0; k < 32; k++) {
            float4 a0 = *(const float4*)&XS(k, warp*8);
            float4 a1 = *(const float4*)&XS(k, warp*8 + 4);
            float4 wv = *(const float4*)&WS(k, lane*4);
            float a[8] = {a0.x,a0.y,a0.z,a0.w,a1.x,a1.y,a1.z,a1.w};
            float bb[4] = {wv.x,wv.y,wv.z,wv.w};
            #pragma unroll
            for (int r = 0; r < 8; r++)
                #pragma unroll
                for (int c = 0; c < 4; c++)
                    acc[r][c] = fmaf(a[r], bb[c], acc[r][c]);
        }
        __syncthreads();
    }

    if (!FINAL) {
        #pragma unroll
        for (int r = 0; r < 8; r++) {
            float4 v;
            v.x = tanhf(acc[r][0] + bv.x);
            v.y = tanhf(acc[r][1] + bv.y);
            v.z = tanhf(acc[r][2] + bv.z);
            v.w = tanhf(acc[r][3] + bv.w);
            *(float4*)(g_h + (row0 + warp*8 + r) * HH + lane*4) = v;
        }
    } else {
        #pragma unroll
        for (int r = 0; r < 8; r++) {
            float4 v;
            v.x = tanhf(acc[r][0] + bv.x);
            v.y = tanhf(acc[r][1] + bv.y);
            v.z = tanhf(acc[r][2] + bv.z);
            v.w = tanhf(acc[r][3] + bv.w);
            *(float4*)&HS(warp*8 + r, lane*4) = v;
        }
        __syncthreads();
        float wreg[32];                           // Wout rows lane*4..+3 (8 outs each)
        #pragma unroll
        for (int i = 0; i < 8; i++)
            *(float4*)&wreg[i*4] = *(const float4*)(Wout + lane * 32 + i * 4);
        #pragma unroll
        for (int rr = 0; rr < 8; rr++) {
            int row = warp * 8 + rr;
            float4 hv = *(const float4*)&HS(row, lane*4);
            float hk[4] = {hv.x, hv.y, hv.z, hv.w};
            float a2[8];
            #pragma unroll
            for (int o = 0; o < 8; o++) a2[o] = 0.f;
            #pragma unroll
            for (int j = 0; j < 4; j++)
                #pragma unroll
                for (int o = 0; o < 8; o++)
                    a2[o] = fmaf(hk[j], wreg[j*8 + o], a2[o]);
            #pragma unroll
            for (int o = 0; o < 8; o++)
                #pragma unroll
                for (int s = 16; s >= 1; s >>= 1)
                    a2[o] += __shfl_xor_sync(0xffffffffu, a2[o], s);
            if (lane == 0) {
                int m = row0 + row;
                float mf = g_maskf[m];
                #pragma unroll
                for (int o = 0; o < 8; o++)
                    out[m * OUTD + o] = (a2[o] + bout[o]) * mf;
            }
        }
    }
}

// ---------------- launch ------------------------------------------------------
extern "C" void kernel_launch(void* const* d_in, const int* in_sizes, int n_in,
                              void* d_out, int out_size) {
    const float* obs  = (const float*)d_in[0];
    const float* W1   = (const float*)d_in[1];
    const float* b1   = (const float*)d_in[2];
    const float* W2   = (const float*)d_in[3];
    const float* b2   = (const float*)d_in[4];
    const float* Wout = (const float*)d_in[5];
    const float* bout = (const float*)d_in[6];
    float* out = (float*)d_out;

    prep_kernel   <<<NODES/256, 256>>>(obs);
    topk_kernel   <<<dim3(NN/8, BB), 256>>>();      // kNN + fused scatter
    listify_kernel<<<NODES/8, 256>>>();

    pregather_kernel<DD, true> <<<NODES/8, 128>>>(obs);              // 64-dim gather -> g_a
    gemm_kernel<DD, false><<<NODES/64, 256>>>(W1, b1, 0, 0, 0);      // g_a @ W1 -> g_h (tanh)
    pregather_kernel<HH, false><<<NODES/4, 128>>>(obs);              // 128-dim gather g_h -> g_a
    gemm_kernel<HH, true><<<NODES/64, 256>>>(W2, b2, Wout, bout, out); // -> out
}